// round 13
// baseline (speedup 1.0000x reference)
#include <cuda_runtime.h>
#include <cuda_bf16.h>
#include <math.h>
#include <stdint.h>

constexpr int B_ = 8;
constexpr int N_ = 1024;
constexpr int D_ = 256;

// ---------------- scratch (bf16 hi/lo pairs; 16B-aligned for vector I/O) -----
__device__ __align__(16) __nv_bfloat16 g_xhi[(size_t)B_ * N_ * D_];
__device__ __align__(16) __nv_bfloat16 g_xlo[(size_t)B_ * N_ * D_];
__device__ __align__(16) __nv_bfloat16 g_yhi[(size_t)B_ * N_ * D_];
__device__ __align__(16) __nv_bfloat16 g_ylo[(size_t)B_ * N_ * D_];
__device__ __align__(16) __nv_bfloat16 g_U12Thi[2 * D_ * D_];
__device__ __align__(16) __nv_bfloat16 g_U12Tlo[2 * D_ * D_];
__device__ __align__(16) __nv_bfloat16 g_UThi[D_ * D_];
__device__ __align__(16) __nv_bfloat16 g_UTlo[D_ * D_];
__device__ __align__(16) __nv_bfloat16 g_Whi[2 * D_ * D_];
__device__ __align__(16) __nv_bfloat16 g_Wlo[2 * D_ * D_];
__device__ __align__(16) __nv_bfloat16 g_xshi[(size_t)B_ * N_ * 2 * D_];
__device__ __align__(16) __nv_bfloat16 g_xslo[(size_t)B_ * N_ * 2 * D_];
__device__ __align__(16) __nv_bfloat16 g_scoreshi[(size_t)B_ * 2 * N_ * N_];
__device__ __align__(16) __nv_bfloat16 g_scoreslo[(size_t)B_ * 2 * N_ * N_];
__device__ __align__(16) __nv_bfloat16 g_attnhi[(size_t)B_ * N_ * N_];
__device__ __align__(16) __nv_bfloat16 g_attnlo[(size_t)B_ * N_ * N_];
__device__ __align__(16) __nv_bfloat16 g_yThi[(size_t)B_ * D_ * N_];
__device__ __align__(16) __nv_bfloat16 g_yTlo[(size_t)B_ * D_ * N_];
__device__ __align__(16) float g_pos[(size_t)N_ * N_];

// ---------------- helpers ----------------
__device__ __forceinline__ uint32_t smaddr(const void* p) {
    return (uint32_t)__cvta_generic_to_shared(p);
}
__device__ __forceinline__ void ldm_x4(uint32_t* r, uint32_t addr) {
    asm volatile("ldmatrix.sync.aligned.m8n8.x4.shared.b16 {%0,%1,%2,%3}, [%4];"
                 : "=r"(r[0]), "=r"(r[1]), "=r"(r[2]), "=r"(r[3]) : "r"(addr));
}
__device__ __forceinline__ void mma_bf16(float* c, const uint32_t* a, const uint32_t* b) {
    asm volatile("mma.sync.aligned.m16n8k16.row.col.f32.bf16.bf16.f32 "
                 "{%0,%1,%2,%3}, {%4,%5,%6,%7}, {%8,%9}, {%0,%1,%2,%3};"
                 : "+f"(c[0]), "+f"(c[1]), "+f"(c[2]), "+f"(c[3])
                 : "r"(a[0]), "r"(a[1]), "r"(a[2]), "r"(a[3]), "r"(b[0]), "r"(b[1]));
}
__device__ __forceinline__ void bsplit(float v, __nv_bfloat16& h, __nv_bfloat16& l) {
    h = __float2bfloat16(v);
    l = __float2bfloat16(v - __bfloat162float(h));
}
// pack (a,b) -> bf16x2 word with a in LOW half
__device__ __forceinline__ uint32_t bpack(float a, float b) {
    uint32_t r;
    asm("cvt.rn.bf16x2.f32 %0, %1, %2;" : "=r"(r) : "f"(b), "f"(a));
    return r;
}
// hi/lo bf16x2 word pair -> two fp32 reconstructed values
__device__ __forceinline__ void bunpack2(uint32_t hp, uint32_t lp, float& v0, float& v1) {
    v0 = __uint_as_float(hp << 16) + __uint_as_float(lp << 16);
    v1 = __uint_as_float(hp & 0xffff0000u) + __uint_as_float(lp & 0xffff0000u);
}
__device__ __forceinline__ void cpa16(uint32_t dst, const void* src) {
    asm volatile("cp.async.cg.shared.global [%0], [%1], 16;" :: "r"(dst), "l"(src));
}
__device__ __forceinline__ void cp_commit() {
    asm volatile("cp.async.commit_group;" ::: "memory");
}
template <int n>
__device__ __forceinline__ void cp_wait() {
    asm volatile("cp.async.wait_group %0;" :: "n"(n) : "memory");
}

__device__ __forceinline__ float blk_max(float v, volatile float* sm) {
    #pragma unroll
    for (int o = 16; o > 0; o >>= 1) v = fmaxf(v, __shfl_xor_sync(0xffffffffu, v, o));
    if ((threadIdx.x & 31) == 0) sm[threadIdx.x >> 5] = v;
    __syncthreads();
    float r = sm[0];
    #pragma unroll
    for (int i = 1; i < 8; i++) r = fmaxf(r, sm[i]);
    __syncthreads();
    return r;
}
__device__ __forceinline__ float blk_sum(float v, volatile float* sm) {
    #pragma unroll
    for (int o = 16; o > 0; o >>= 1) v += __shfl_xor_sync(0xffffffffu, v, o);
    if ((threadIdx.x & 31) == 0) sm[threadIdx.x >> 5] = v;
    __syncthreads();
    float r = sm[0];
    #pragma unroll
    for (int i = 1; i < 8; i++) r += sm[i];
    __syncthreads();
    return r;
}

// ---------------- NT GEMM, 3xBF16 with pre-split operands --------------------
// EPI: 0 = fp32 store to C; 1 = bf16 hi/lo split store to Chi/Clo.
template <int BN, int NS, int EPI>
__device__ __forceinline__ void gemm_b3(
    const __nv_bfloat16* __restrict__ Ahi, const __nv_bfloat16* __restrict__ Alo, int lda,
    const __nv_bfloat16* __restrict__ Bhi, const __nv_bfloat16* __restrict__ Blo, int ldb,
    float* __restrict__ C, __nv_bfloat16* __restrict__ Chi, __nv_bfloat16* __restrict__ Clo,
    int ldc, int K, float alpha)
{
    constexpr int BM = 128, BK = 32;
    constexpr int APL = BM * 64;
    constexpr int BPL = BN * 64;
    constexpr int STG = 2 * APL + 2 * BPL;
    constexpr int WN = BN / 2, nP = BN / 32;

    extern __shared__ float smem[];
    const uint32_t sbase = smaddr(smem);

    const int tid = threadIdx.x, lane = tid & 31, warp = tid >> 5;
    const int wm = (warp & 3) * 32, wn = (warp >> 2) * WN;
    const int m0 = blockIdx.y * BM, n0 = blockIdx.x * BN;

    const int ar = tid >> 1;
    const int ac0 = (tid & 1) * 2;
    const __nv_bfloat16* aHs = Ahi + (size_t)(m0 + ar) * lda + ac0 * 8;
    const __nv_bfloat16* aLs = Alo + (size_t)(m0 + ar) * lda + ac0 * 8;
    const int asw_st = (ar >> 1) & 3;
    const uint32_t aH0 = sbase + ar * 64 + ((ac0 ^ asw_st) * 16);
    const uint32_t aH1 = sbase + ar * 64 + (((ac0 + 1) ^ asw_st) * 16);

    const int br = (BN == 128) ? (tid >> 1) : (tid >> 2);
    const int bc0 = (BN == 128) ? ((tid & 1) * 2) : (tid & 3);
    const __nv_bfloat16* bHs = Bhi + (size_t)(n0 + br) * ldb + bc0 * 8;
    const __nv_bfloat16* bLs = Blo + (size_t)(n0 + br) * ldb + bc0 * 8;
    const int bsw_st = (br >> 1) & 3;
    const uint32_t bH0 = sbase + 2 * APL + br * 64 + ((bc0 ^ bsw_st) * 16);
    const uint32_t bH1 = sbase + 2 * APL + br * 64 + (((bc0 + 1) ^ bsw_st) * 16);

    auto issue = [&](int kt, int slot) {
        const uint32_t so = (uint32_t)slot * STG;
        const int ko = kt * BK;
        cpa16(aH0 + so, aHs + ko);
        cpa16(aH1 + so, aHs + ko + 8);
        cpa16(aH0 + so + APL, aLs + ko);
        cpa16(aH1 + so + APL, aLs + ko + 8);
        cpa16(bH0 + so, bHs + ko);
        cpa16(bH0 + so + BPL, bLs + ko);
        if (BN == 128) {
            cpa16(bH1 + so, bHs + ko + 8);
            cpa16(bH1 + so + BPL, bLs + ko + 8);
        }
    };

    const int mat = lane >> 3, idx = lane & 7;
    const int arow = wm + (mat & 1) * 8 + idx;
    const int asw = (arow >> 1) & 3;
    const int ach = mat >> 1;
    const uint32_t aK0 = (uint32_t)((ach ^ asw) * 16);
    const uint32_t aK1 = (uint32_t)(((ach + 2) ^ asw) * 16);
    const uint32_t aHiB = sbase + arow * 64;

    const int brow = wn + (mat >> 1) * 8 + idx;
    const int bsw = (brow >> 1) & 3;
    const int bch = mat & 1;
    const uint32_t bK0 = (uint32_t)((bch ^ bsw) * 16);
    const uint32_t bK1 = (uint32_t)(((bch + 2) ^ bsw) * 16);
    const uint32_t bHiB = sbase + 2 * APL + brow * 64;

    float acc[2][2 * nP][4] = {};

    const int ktiles = K / BK;
    #pragma unroll
    for (int s = 0; s < NS - 1; s++) { issue(s, s); cp_commit(); }

    for (int kt = 0; kt < ktiles; kt++) {
        cp_wait<NS - 2>();
        __syncthreads();
        const uint32_t so = (uint32_t)(kt % NS) * STG;

        if (kt + NS - 1 < ktiles) issue(kt + NS - 1, (kt + NS - 1) % NS);
        cp_commit();

        #pragma unroll
        for (int s16 = 0; s16 < 2; s16++) {
            const uint32_t akk = s16 ? aK1 : aK0;
            const uint32_t bkk = s16 ? bK1 : bK0;
            uint32_t ah[2][4], al[2][4];
            ldm_x4(ah[0], aHiB + so + akk);
            ldm_x4(ah[1], aHiB + so + akk + 16 * 64);
            ldm_x4(al[0], aHiB + so + akk + APL);
            ldm_x4(al[1], aHiB + so + akk + APL + 16 * 64);

            #pragma unroll
            for (int pg = 0; pg < nP; pg += 2) {
                uint32_t bh[2][4], bl[2][4];
                #pragma unroll
                for (int pp = 0; pp < 2; pp++) {
                    ldm_x4(bh[pp], bHiB + so + bkk + (pg + pp) * 16 * 64);
                    ldm_x4(bl[pp], bHiB + so + bkk + (pg + pp) * 16 * 64 + BPL);
                }
                #pragma unroll
                for (int pp = 0; pp < 2; pp++)
                    #pragma unroll
                    for (int f = 0; f < 2; f++) {
                        mma_bf16(acc[f][2 * (pg + pp)],     ah[f], bh[pp]);
                        mma_bf16(acc[f][2 * (pg + pp) + 1], ah[f], bh[pp] + 2);
                    }
                #pragma unroll
                for (int pp = 0; pp < 2; pp++)
                    #pragma unroll
                    for (int f = 0; f < 2; f++) {
                        mma_bf16(acc[f][2 * (pg + pp)],     ah[f], bl[pp]);
                        mma_bf16(acc[f][2 * (pg + pp) + 1], ah[f], bl[pp] + 2);
                    }
                #pragma unroll
                for (int pp = 0; pp < 2; pp++)
                    #pragma unroll
                    for (int f = 0; f < 2; f++) {
                        mma_bf16(acc[f][2 * (pg + pp)],     al[f], bh[pp]);
                        mma_bf16(acc[f][2 * (pg + pp) + 1], al[f], bh[pp] + 2);
                    }
            }
        }
    }

    const int g = lane >> 2, tig = lane & 3;
    #pragma unroll
    for (int f = 0; f < 2; f++) {
        #pragma unroll
        for (int q = 0; q < 2 * nP; q++) {
            const int r = m0 + wm + f * 16 + g;
            const int c = n0 + wn + q * 8 + tig * 2;
            #pragma unroll
            for (int h = 0; h < 2; h++) {
                const int rr = r + h * 8;
                float v0 = alpha * acc[f][q][2 * h];
                float v1 = alpha * acc[f][q][2 * h + 1];
                if (EPI == 0) {
                    *(float2*)(C + (size_t)rr * ldc + c) = make_float2(v0, v1);
                } else {
                    uint32_t hp = bpack(v0, v1);
                    float h0 = __uint_as_float(hp << 16);
                    float h1 = __uint_as_float(hp & 0xffff0000u);
                    uint32_t lp = bpack(v0 - h0, v1 - h1);
                    *(uint32_t*)(Chi + (size_t)rr * ldc + c) = hp;
                    *(uint32_t*)(Clo + (size_t)rr * ldc + c) = lp;
                }
            }
        }
    }
}

// smem bytes (NS=3)
constexpr int SMB128 = 3 * (2 * 128 * 64 + 2 * 128 * 64);  // 98304
constexpr int SMB64  = 3 * (2 * 128 * 64 + 2 * 64 * 64);   // 73728

// ---------------- GEMM wrappers ----------------
__global__ void __launch_bounds__(256, 3)
k_g_w() {
    gemm_b3<64, 3, 1>(g_U12Thi, g_U12Tlo, D_, g_UThi, g_UTlo, D_,
                      nullptr, g_Whi, g_Wlo, D_, D_, 1.0f);
}
__global__ void __launch_bounds__(256, 2)
k_gemm_xs() {
    gemm_b3<128, 3, 1>(g_xhi, g_xlo, D_, g_Whi, g_Wlo, D_,
                       nullptr, g_xshi, g_xslo, 2 * D_, D_, 1.0f);
}
__global__ void __launch_bounds__(256, 2)
k_gemm_scores() {
    int z = blockIdx.z;
    int b = z >> 1, k = z & 1;
    gemm_b3<128, 3, 1>(g_xshi + (size_t)b * N_ * (2 * D_) + k * D_,
                       g_xslo + (size_t)b * N_ * (2 * D_) + k * D_, 2 * D_,
                       g_yhi + (size_t)b * N_ * D_, g_ylo + (size_t)b * N_ * D_, D_,
                       nullptr,
                       g_scoreshi + (size_t)z * N_ * N_,
                       g_scoreslo + (size_t)z * N_ * N_, N_,
                       D_, 0.0625f);
}
__global__ void __launch_bounds__(256, 3)
k_gemm_out(float* __restrict__ out) {
    int b = blockIdx.z;
    gemm_b3<64, 3, 0>(g_attnhi + (size_t)b * N_ * N_, g_attnlo + (size_t)b * N_ * N_, N_,
                      g_yThi + (size_t)b * D_ * N_, g_yTlo + (size_t)b * D_ * N_, N_,
                      out + (size_t)b * N_ * D_, nullptr, nullptr, D_,
                      N_, 1.0f);
}

// ---------------- prep kernels ----------------
__global__ void k_prep_u(const float* __restrict__ U,
                         const float* __restrict__ S1,
                         const float* __restrict__ S2) {
    int i = blockIdx.x * 256 + threadIdx.x;   // 512*256
    int r = i >> 8, d = i & 255;
    int k = r >> 8, j = r & 255;
    float v = fabsf(k ? S2[d] : S1[d]) * U[d * 256 + j];
    bsplit(v, g_U12Thi[i], g_U12Tlo[i]);
}

__global__ void k_transpose_u(const float* __restrict__ U) {
    __shared__ float tile[32][33];
    int d0 = blockIdx.y * 32, i0 = blockIdx.x * 32;
    int tx = threadIdx.x, ty = threadIdx.y;
    #pragma unroll
    for (int r = ty; r < 32; r += 8)
        tile[r][tx] = U[(d0 + r) * D_ + i0 + tx];
    __syncthreads();
    #pragma unroll
    for (int r = ty; r < 32; r += 8)
        bsplit(tile[tx][r], g_UThi[(i0 + r) * D_ + d0 + tx], g_UTlo[(i0 + r) * D_ + d0 + tx]);
}

// vectorized split: 4 elems/thread
__global__ void k_split_x(const float* __restrict__ x) {
    int i4 = (blockIdx.x * 256 + threadIdx.x) * 4;
    float4 v = *(const float4*)(x + i4);
    uint32_t hp0 = bpack(v.x, v.y);
    uint32_t hp1 = bpack(v.z, v.w);
    float hx = __uint_as_float(hp0 << 16);
    float hy = __uint_as_float(hp0 & 0xffff0000u);
    float hz = __uint_as_float(hp1 << 16);
    float hw = __uint_as_float(hp1 & 0xffff0000u);
    uint32_t lp0 = bpack(v.x - hx, v.y - hy);
    uint32_t lp1 = bpack(v.z - hz, v.w - hw);
    *(uint2*)(g_xhi + i4) = make_uint2(hp0, hp1);
    *(uint2*)(g_xlo + i4) = make_uint2(lp0, lp1);
}

// fused + vectorized: y -> (yhi,ylo) + (yThi,yTlo), bf16x2 stores only.
// Block = 16x16 threads, tile = 32(m) x 32(j).
__global__ void k_prep_y(const float* __restrict__ y) {
    __shared__ float tile[32][33];
    int b = blockIdx.z;
    int m0 = blockIdx.y * 32, j0 = blockIdx.x * 32;
    int tx = threadIdx.x, ty = threadIdx.y;   // 16 x 16
    // phase 1: direct layout; thread owns 2 consecutive j
    #pragma unroll
    for (int ii = 0; ii < 2; ii++) {
        int i = ty + ii * 16;
        size_t o = ((size_t)b * N_ + m0 + i) * D_ + j0 + 2 * tx;
        float2 v = *(const float2*)(y + o);
        tile[i][2 * tx] = v.x;
        tile[i][2 * tx + 1] = v.y;
        uint32_t hp = bpack(v.x, v.y);
        float h0 = __uint_as_float(hp << 16);
        float h1 = __uint_as_float(hp & 0xffff0000u);
        uint32_t lp = bpack(v.x - h0, v.y - h1);
        *(uint32_t*)(g_yhi + o) = hp;
        *(uint32_t*)(g_ylo + o) = lp;
    }
    __syncthreads();
    // phase 2: transposed layout; thread owns 2 consecutive m
    #pragma unroll
    for (int jj = 0; jj < 2; jj++) {
        int j = ty + jj * 16;
        float a = tile[2 * tx][j];
        float c = tile[2 * tx + 1][j];
        uint32_t hp = bpack(a, c);
        float h0 = __uint_as_float(hp << 16);
        float h1 = __uint_as_float(hp & 0xffff0000u);
        uint32_t lp = bpack(a - h0, c - h1);
        size_t o = ((size_t)b * D_ + j0 + j) * N_ + m0 + 2 * tx;
        *(uint32_t*)(g_yThi + o) = hp;
        *(uint32_t*)(g_yTlo + o) = lp;
    }
}

__global__ void k_pos(const float* __restrict__ coords,
                      const float* __restrict__ pos_emb,
                      const float* __restrict__ p_temp) {
    __shared__ float pe[6];
    __shared__ float sm[8];
    int n = blockIdx.x;
    int t = threadIdx.x;
    if (t < 6) pe[t] = pos_emb[n * 6 + t];
    __syncthreads();
    float pt = -fabsf(p_temp[0]);
    float lg[4];
    float lmax = -1e30f;
    #pragma unroll
    for (int i = 0; i < 4; i++) {
        int m = i * 256 + t;
        const float* c = coords + ((size_t)n * N_ + m) * 6;
        float a = c[0] * pe[0] + c[1] * pe[1] + c[2] * pe[2]
                + c[3] * pe[3] + c[4] * pe[4] + c[5] * pe[5];
        lg[i] = pt * a;
        lmax = fmaxf(lmax, lg[i]);
    }
    float mx = blk_max(lmax, sm);
    float lsum = 0.f;
    #pragma unroll
    for (int i = 0; i < 4; i++) { lg[i] = __expf(lg[i] - mx); lsum += lg[i]; }
    float s = blk_sum(lsum, sm);
    float inv = 1.0f / s;
    #pragma unroll
    for (int i = 0; i < 4; i++)
        g_pos[(size_t)n * N_ + i * 256 + t] = lg[i] * inv;
}

// vectorized mix: thread t owns 4 consecutive m; scores read as bf16 hi/lo
__global__ void k_mix(const float* __restrict__ gating,
                      const float* __restrict__ h_temp,
                      float* __restrict__ heat) {
    __shared__ float sm[8];
    int bn = blockIdx.x;
    int b = bn >> 10;
    int n = bn & (N_ - 1);
    int t = threadIdx.x;

    size_t base0 = ((size_t)(b * 2 + 0) * N_ + n) * N_ + 4 * t;
    size_t base1 = ((size_t)(b * 2 + 1) * N_ + n) * N_ + 4 * t;

    uint2 h0v = *(const uint2*)(g_scoreshi + base0);
    uint2 l0v = *(const uint2*)(g_scoreslo + base0);
    uint2 h1v = *(const uint2*)(g_scoreshi + base1);
    uint2 l1v = *(const uint2*)(g_scoreslo + base1);
    float4 vp = *(const float4*)(g_pos + (size_t)n * N_ + 4 * t);

    float s0[4], s1[4];
    bunpack2(h0v.x, l0v.x, s0[0], s0[1]);
    bunpack2(h0v.y, l0v.y, s0[2], s0[3]);
    bunpack2(h1v.x, l1v.x, s1[0], s1[1]);
    bunpack2(h1v.y, l1v.y, s1[2], s1[3]);
    float pp[4] = {vp.x, vp.y, vp.z, vp.w};

    float lm0 = fmaxf(fmaxf(s0[0], s0[1]), fmaxf(s0[2], s0[3]));
    float lm1 = fmaxf(fmaxf(s1[0], s1[1]), fmaxf(s1[2], s1[3]));
    float mx0 = blk_max(lm0, sm);
    float mx1 = blk_max(lm1, sm);

    float ls0 = 0.f, ls1 = 0.f;
    #pragma unroll
    for (int i = 0; i < 4; i++) {
        s0[i] = __expf(s0[i] - mx0); ls0 += s0[i];
        s1[i] = __expf(s1[i] - mx1); ls1 += s1[i];
    }
    float sum0 = blk_sum(ls0, sm);
    float sum1 = blk_sum(ls1, sm);
    float inv0 = 1.0f / sum0, inv1 = 1.0f / sum1;

    float g = 1.0f / (1.0f + __expf(-gating[0]));
    float og = 1.0f - g;

    float p0[4], p1[4];
    float le0 = 0.f, le1 = 0.f;
    #pragma unroll
    for (int i = 0; i < 4; i++) {
        p0[i] = og * s0[i] * inv0 + g * pp[i];
        p1[i] = og * s1[i] * inv1 + g * pp[i];
        le0 -= p0[i] * __logf(p0[i] + 1e-8f);
        le1 -= p1[i] * __logf(p1[i] + 1e-8f);
    }
    float ent0 = blk_sum(le0, sm);
    float ent1 = blk_sum(le1, sm);

    float ht = h_temp[0];
    float hm0 = 2.0f - 2.0f / (1.0f + __expf(-ht * ent0));
    float hm1 = 2.0f - 2.0f / (1.0f + __expf(-ht * ent1));
    int sel = (hm0 >= hm1) ? 0 : 1;

    const float* ps = sel ? p1 : p0;
    uint32_t hp0 = bpack(ps[0], ps[1]);
    uint32_t hp1 = bpack(ps[2], ps[3]);
    float h0 = __uint_as_float(hp0 << 16);
    float h1 = __uint_as_float(hp0 & 0xffff0000u);
    float h2 = __uint_as_float(hp1 << 16);
    float h3 = __uint_as_float(hp1 & 0xffff0000u);
    uint32_t lp0 = bpack(ps[0] - h0, ps[1] - h1);
    uint32_t lp1 = bpack(ps[2] - h2, ps[3] - h3);
    size_t ob = (size_t)bn * N_ + 4 * t;
    *(uint2*)(g_attnhi + ob) = make_uint2(hp0, hp1);
    *(uint2*)(g_attnlo + ob) = make_uint2(lp0, lp1);

    if (t == 0) heat[bn] = sel ? hm1 : hm0;
}

// ---------------- launch ----------------
extern "C" void kernel_launch(void* const* d_in, const int* in_sizes, int n_in,
                              void* d_out, int out_size) {
    const float* x       = (const float*)d_in[0];
    const float* y       = (const float*)d_in[1];
    const float* coords  = (const float*)d_in[2];
    const float* U       = (const float*)d_in[3];
    const float* S1      = (const float*)d_in[4];
    const float* S2      = (const float*)d_in[5];
    const float* gating  = (const float*)d_in[6];
    const float* h_temp  = (const float*)d_in[7];
    const float* p_temp  = (const float*)d_in[8];
    const float* pos_emb = (const float*)d_in[9];

    float* out  = (float*)d_out;
    float* heat = out + (size_t)B_ * N_ * D_;

    cudaFuncSetAttribute(k_g_w,         cudaFuncAttributeMaxDynamicSharedMemorySize, SMB64);
    cudaFuncSetAttribute(k_gemm_xs,     cudaFuncAttributeMaxDynamicSharedMemorySize, SMB128);
    cudaFuncSetAttribute(k_gemm_scores, cudaFuncAttributeMaxDynamicSharedMemorySize, SMB128);
    cudaFuncSetAttribute(k_gemm_out,    cudaFuncAttributeMaxDynamicSharedMemorySize, SMB64);

    // prep / splits
    k_prep_u<<<(2 * D_ * D_) / 256, 256>>>(U, S1, S2);
    k_transpose_u<<<dim3(D_ / 32, D_ / 32), dim3(32, 8)>>>(U);
    k_split_x<<<(B_ * N_ * D_) / 1024, 256>>>(x);
    k_prep_y<<<dim3(D_ / 32, N_ / 32, B_), dim3(16, 16)>>>(y);
    k_pos<<<N_, 256>>>(coords, pos_emb, p_temp);

    // W = U^T diag|S| U (both branches)  [512 x 256]
    k_g_w<<<dim3(D_ / 64, (2 * D_) / 128), 256, SMB64>>>();

    // xs = x @ W
    k_gemm_xs<<<dim3((2 * D_) / 128, (B_ * N_) / 128), 256, SMB128>>>();

    // patch logits -> bf16 hi/lo
    k_gemm_scores<<<dim3(N_ / 128, N_ / 128, B_ * 2), 256, SMB128>>>();

    // softmax/blend/entropy/route
    k_mix<<<B_ * N_, 256>>>(gating, h_temp, heat);

    // out = attn_sel @ y
    k_gemm_out<<<dim3(D_ / 64, N_ / 128, B_), 256, SMB64>>>(out);
}

// round 14
// speedup vs baseline: 1.0462x; 1.0462x over previous
#include <cuda_runtime.h>
#include <cuda_bf16.h>
#include <math.h>
#include <stdint.h>

constexpr int B_ = 8;
constexpr int N_ = 1024;
constexpr int D_ = 256;

// ---------------- scratch (bf16 hi/lo pairs; 16B-aligned for vector I/O) -----
__device__ __align__(16) __nv_bfloat16 g_xhi[(size_t)B_ * N_ * D_];
__device__ __align__(16) __nv_bfloat16 g_xlo[(size_t)B_ * N_ * D_];
__device__ __align__(16) __nv_bfloat16 g_yhi[(size_t)B_ * N_ * D_];
__device__ __align__(16) __nv_bfloat16 g_ylo[(size_t)B_ * N_ * D_];
__device__ __align__(16) __nv_bfloat16 g_U12Thi[2 * D_ * D_];
__device__ __align__(16) __nv_bfloat16 g_U12Tlo[2 * D_ * D_];
__device__ __align__(16) __nv_bfloat16 g_UThi[D_ * D_];
__device__ __align__(16) __nv_bfloat16 g_UTlo[D_ * D_];
__device__ __align__(16) __nv_bfloat16 g_Whi[2 * D_ * D_];
__device__ __align__(16) __nv_bfloat16 g_Wlo[2 * D_ * D_];
__device__ __align__(16) __nv_bfloat16 g_xshi[(size_t)B_ * N_ * 2 * D_];
__device__ __align__(16) __nv_bfloat16 g_xslo[(size_t)B_ * N_ * 2 * D_];
__device__ __align__(16) __nv_bfloat16 g_attnhi[(size_t)B_ * N_ * N_];
__device__ __align__(16) __nv_bfloat16 g_attnlo[(size_t)B_ * N_ * N_];
__device__ __align__(16) __nv_bfloat16 g_yThi[(size_t)B_ * D_ * N_];
__device__ __align__(16) __nv_bfloat16 g_yTlo[(size_t)B_ * D_ * N_];
__device__ __align__(16) float g_pos[(size_t)N_ * N_];
__device__ __align__(16) float g_scores[(size_t)B_ * 2 * N_ * N_];

// ---------------- helpers ----------------
__device__ __forceinline__ uint32_t smaddr(const void* p) {
    return (uint32_t)__cvta_generic_to_shared(p);
}
__device__ __forceinline__ void ldm_x4(uint32_t* r, uint32_t addr) {
    asm volatile("ldmatrix.sync.aligned.m8n8.x4.shared.b16 {%0,%1,%2,%3}, [%4];"
                 : "=r"(r[0]), "=r"(r[1]), "=r"(r[2]), "=r"(r[3]) : "r"(addr));
}
__device__ __forceinline__ void mma_bf16(float* c, const uint32_t* a, const uint32_t* b) {
    asm volatile("mma.sync.aligned.m16n8k16.row.col.f32.bf16.bf16.f32 "
                 "{%0,%1,%2,%3}, {%4,%5,%6,%7}, {%8,%9}, {%0,%1,%2,%3};"
                 : "+f"(c[0]), "+f"(c[1]), "+f"(c[2]), "+f"(c[3])
                 : "r"(a[0]), "r"(a[1]), "r"(a[2]), "r"(a[3]), "r"(b[0]), "r"(b[1]));
}
__device__ __forceinline__ void bsplit(float v, __nv_bfloat16& h, __nv_bfloat16& l) {
    h = __float2bfloat16(v);
    l = __float2bfloat16(v - __bfloat162float(h));
}
// pack (a,b) -> bf16x2 word with a in LOW half
__device__ __forceinline__ uint32_t bpack(float a, float b) {
    uint32_t r;
    asm("cvt.rn.bf16x2.f32 %0, %1, %2;" : "=r"(r) : "f"(b), "f"(a));
    return r;
}
__device__ __forceinline__ void cpa16(uint32_t dst, const void* src) {
    asm volatile("cp.async.cg.shared.global [%0], [%1], 16;" :: "r"(dst), "l"(src));
}
__device__ __forceinline__ void cp_commit() {
    asm volatile("cp.async.commit_group;" ::: "memory");
}
template <int n>
__device__ __forceinline__ void cp_wait() {
    asm volatile("cp.async.wait_group %0;" :: "n"(n) : "memory");
}

__device__ __forceinline__ float blk_max(float v, volatile float* sm) {
    #pragma unroll
    for (int o = 16; o > 0; o >>= 1) v = fmaxf(v, __shfl_xor_sync(0xffffffffu, v, o));
    if ((threadIdx.x & 31) == 0) sm[threadIdx.x >> 5] = v;
    __syncthreads();
    float r = sm[0];
    #pragma unroll
    for (int i = 1; i < 8; i++) r = fmaxf(r, sm[i]);
    __syncthreads();
    return r;
}
__device__ __forceinline__ float blk_sum(float v, volatile float* sm) {
    #pragma unroll
    for (int o = 16; o > 0; o >>= 1) v += __shfl_xor_sync(0xffffffffu, v, o);
    if ((threadIdx.x & 31) == 0) sm[threadIdx.x >> 5] = v;
    __syncthreads();
    float r = sm[0];
    #pragma unroll
    for (int i = 1; i < 8; i++) r += sm[i];
    __syncthreads();
    return r;
}

// ---------------- NT GEMM, 3xBF16 with pre-split operands --------------------
// EPI: 0 = fp32 store to C; 1 = bf16 hi/lo split store to Chi/Clo.
template <int BN, int NS, int EPI>
__device__ __forceinline__ void gemm_b3(
    const __nv_bfloat16* __restrict__ Ahi, const __nv_bfloat16* __restrict__ Alo, int lda,
    const __nv_bfloat16* __restrict__ Bhi, const __nv_bfloat16* __restrict__ Blo, int ldb,
    float* __restrict__ C, __nv_bfloat16* __restrict__ Chi, __nv_bfloat16* __restrict__ Clo,
    int ldc, int K, float alpha)
{
    constexpr int BM = 128, BK = 32;
    constexpr int APL = BM * 64;
    constexpr int BPL = BN * 64;
    constexpr int STG = 2 * APL + 2 * BPL;
    constexpr int WN = BN / 2, nP = BN / 32;

    extern __shared__ float smem[];
    const uint32_t sbase = smaddr(smem);

    const int tid = threadIdx.x, lane = tid & 31, warp = tid >> 5;
    const int wm = (warp & 3) * 32, wn = (warp >> 2) * WN;
    const int m0 = blockIdx.y * BM, n0 = blockIdx.x * BN;

    const int ar = tid >> 1;
    const int ac0 = (tid & 1) * 2;
    const __nv_bfloat16* aHs = Ahi + (size_t)(m0 + ar) * lda + ac0 * 8;
    const __nv_bfloat16* aLs = Alo + (size_t)(m0 + ar) * lda + ac0 * 8;
    const int asw_st = (ar >> 1) & 3;
    const uint32_t aH0 = sbase + ar * 64 + ((ac0 ^ asw_st) * 16);
    const uint32_t aH1 = sbase + ar * 64 + (((ac0 + 1) ^ asw_st) * 16);

    const int br = (BN == 128) ? (tid >> 1) : (tid >> 2);
    const int bc0 = (BN == 128) ? ((tid & 1) * 2) : (tid & 3);
    const __nv_bfloat16* bHs = Bhi + (size_t)(n0 + br) * ldb + bc0 * 8;
    const __nv_bfloat16* bLs = Blo + (size_t)(n0 + br) * ldb + bc0 * 8;
    const int bsw_st = (br >> 1) & 3;
    const uint32_t bH0 = sbase + 2 * APL + br * 64 + ((bc0 ^ bsw_st) * 16);
    const uint32_t bH1 = sbase + 2 * APL + br * 64 + (((bc0 + 1) ^ bsw_st) * 16);

    auto issue = [&](int kt, int slot) {
        const uint32_t so = (uint32_t)slot * STG;
        const int ko = kt * BK;
        cpa16(aH0 + so, aHs + ko);
        cpa16(aH1 + so, aHs + ko + 8);
        cpa16(aH0 + so + APL, aLs + ko);
        cpa16(aH1 + so + APL, aLs + ko + 8);
        cpa16(bH0 + so, bHs + ko);
        cpa16(bH0 + so + BPL, bLs + ko);
        if (BN == 128) {
            cpa16(bH1 + so, bHs + ko + 8);
            cpa16(bH1 + so + BPL, bLs + ko + 8);
        }
    };

    const int mat = lane >> 3, idx = lane & 7;
    const int arow = wm + (mat & 1) * 8 + idx;
    const int asw = (arow >> 1) & 3;
    const int ach = mat >> 1;
    const uint32_t aK0 = (uint32_t)((ach ^ asw) * 16);
    const uint32_t aK1 = (uint32_t)(((ach + 2) ^ asw) * 16);
    const uint32_t aHiB = sbase + arow * 64;

    const int brow = wn + (mat >> 1) * 8 + idx;
    const int bsw = (brow >> 1) & 3;
    const int bch = mat & 1;
    const uint32_t bK0 = (uint32_t)((bch ^ bsw) * 16);
    const uint32_t bK1 = (uint32_t)(((bch + 2) ^ bsw) * 16);
    const uint32_t bHiB = sbase + 2 * APL + brow * 64;

    float acc[2][2 * nP][4] = {};

    const int ktiles = K / BK;
    #pragma unroll
    for (int s = 0; s < NS - 1; s++) { issue(s, s); cp_commit(); }

    for (int kt = 0; kt < ktiles; kt++) {
        cp_wait<NS - 2>();
        __syncthreads();
        const uint32_t so = (uint32_t)(kt % NS) * STG;

        if (kt + NS - 1 < ktiles) issue(kt + NS - 1, (kt + NS - 1) % NS);
        cp_commit();

        #pragma unroll
        for (int s16 = 0; s16 < 2; s16++) {
            const uint32_t akk = s16 ? aK1 : aK0;
            const uint32_t bkk = s16 ? bK1 : bK0;
            uint32_t ah[2][4], al[2][4];
            ldm_x4(ah[0], aHiB + so + akk);
            ldm_x4(ah[1], aHiB + so + akk + 16 * 64);
            ldm_x4(al[0], aHiB + so + akk + APL);
            ldm_x4(al[1], aHiB + so + akk + APL + 16 * 64);

            #pragma unroll
            for (int pg = 0; pg < nP; pg += 2) {
                uint32_t bh[2][4], bl[2][4];
                #pragma unroll
                for (int pp = 0; pp < 2; pp++) {
                    ldm_x4(bh[pp], bHiB + so + bkk + (pg + pp) * 16 * 64);
                    ldm_x4(bl[pp], bHiB + so + bkk + (pg + pp) * 16 * 64 + BPL);
                }
                #pragma unroll
                for (int pp = 0; pp < 2; pp++)
                    #pragma unroll
                    for (int f = 0; f < 2; f++) {
                        mma_bf16(acc[f][2 * (pg + pp)],     ah[f], bh[pp]);
                        mma_bf16(acc[f][2 * (pg + pp) + 1], ah[f], bh[pp] + 2);
                    }
                #pragma unroll
                for (int pp = 0; pp < 2; pp++)
                    #pragma unroll
                    for (int f = 0; f < 2; f++) {
                        mma_bf16(acc[f][2 * (pg + pp)],     ah[f], bl[pp]);
                        mma_bf16(acc[f][2 * (pg + pp) + 1], ah[f], bl[pp] + 2);
                    }
                #pragma unroll
                for (int pp = 0; pp < 2; pp++)
                    #pragma unroll
                    for (int f = 0; f < 2; f++) {
                        mma_bf16(acc[f][2 * (pg + pp)],     al[f], bh[pp]);
                        mma_bf16(acc[f][2 * (pg + pp) + 1], al[f], bh[pp] + 2);
                    }
            }
        }
    }

    const int g = lane >> 2, tig = lane & 3;
    #pragma unroll
    for (int f = 0; f < 2; f++) {
        #pragma unroll
        for (int q = 0; q < 2 * nP; q++) {
            const int r = m0 + wm + f * 16 + g;
            const int c = n0 + wn + q * 8 + tig * 2;
            #pragma unroll
            for (int h = 0; h < 2; h++) {
                const int rr = r + h * 8;
                float v0 = alpha * acc[f][q][2 * h];
                float v1 = alpha * acc[f][q][2 * h + 1];
                if (EPI == 0) {
                    *(float2*)(C + (size_t)rr * ldc + c) = make_float2(v0, v1);
                } else {
                    uint32_t hp = bpack(v0, v1);
                    float h0 = __uint_as_float(hp << 16);
                    float h1 = __uint_as_float(hp & 0xffff0000u);
                    uint32_t lp = bpack(v0 - h0, v1 - h1);
                    *(uint32_t*)(Chi + (size_t)rr * ldc + c) = hp;
                    *(uint32_t*)(Clo + (size_t)rr * ldc + c) = lp;
                }
            }
        }
    }
}

// smem bytes (NS=3)
constexpr int SMB128 = 3 * (2 * 128 * 64 + 2 * 128 * 64);  // 98304
constexpr int SMB64  = 3 * (2 * 128 * 64 + 2 * 64 * 64);   // 73728

// ---------------- GEMM wrappers ----------------
__global__ void __launch_bounds__(256, 3)
k_g_w() {
    gemm_b3<64, 3, 1>(g_U12Thi, g_U12Tlo, D_, g_UThi, g_UTlo, D_,
                      nullptr, g_Whi, g_Wlo, D_, D_, 1.0f);
}
__global__ void __launch_bounds__(256, 2)
k_gemm_xs() {
    gemm_b3<128, 3, 1>(g_xhi, g_xlo, D_, g_Whi, g_Wlo, D_,
                       nullptr, g_xshi, g_xslo, 2 * D_, D_, 1.0f);
}
__global__ void __launch_bounds__(256, 2)
k_gemm_scores() {
    int z = blockIdx.z;
    int b = z >> 1, k = z & 1;
    gemm_b3<128, 3, 0>(g_xshi + (size_t)b * N_ * (2 * D_) + k * D_,
                       g_xslo + (size_t)b * N_ * (2 * D_) + k * D_, 2 * D_,
                       g_yhi + (size_t)b * N_ * D_, g_ylo + (size_t)b * N_ * D_, D_,
                       g_scores + (size_t)z * N_ * N_, nullptr, nullptr, N_,
                       D_, 0.0625f);
}
__global__ void __launch_bounds__(256, 3)
k_gemm_out(float* __restrict__ out) {
    int b = blockIdx.z;
    gemm_b3<64, 3, 0>(g_attnhi + (size_t)b * N_ * N_, g_attnlo + (size_t)b * N_ * N_, N_,
                      g_yThi + (size_t)b * D_ * N_, g_yTlo + (size_t)b * D_ * N_, N_,
                      out + (size_t)b * N_ * D_, nullptr, nullptr, D_,
                      N_, 1.0f);
}

// ---------------- prep kernels ----------------
__global__ void k_prep_u(const float* __restrict__ U,
                         const float* __restrict__ S1,
                         const float* __restrict__ S2) {
    int i = blockIdx.x * 256 + threadIdx.x;   // 512*256
    int r = i >> 8, d = i & 255;
    int k = r >> 8, j = r & 255;
    float v = fabsf(k ? S2[d] : S1[d]) * U[d * 256 + j];
    bsplit(v, g_U12Thi[i], g_U12Tlo[i]);
}

__global__ void k_transpose_u(const float* __restrict__ U) {
    __shared__ float tile[32][33];
    int d0 = blockIdx.y * 32, i0 = blockIdx.x * 32;
    int tx = threadIdx.x, ty = threadIdx.y;
    #pragma unroll
    for (int r = ty; r < 32; r += 8)
        tile[r][tx] = U[(d0 + r) * D_ + i0 + tx];
    __syncthreads();
    #pragma unroll
    for (int r = ty; r < 32; r += 8)
        bsplit(tile[tx][r], g_UThi[(i0 + r) * D_ + d0 + tx], g_UTlo[(i0 + r) * D_ + d0 + tx]);
}

// vectorized split: 4 elems/thread
__global__ void k_split_x(const float* __restrict__ x) {
    int i4 = (blockIdx.x * 256 + threadIdx.x) * 4;
    float4 v = *(const float4*)(x + i4);
    uint32_t hp0 = bpack(v.x, v.y);
    uint32_t hp1 = bpack(v.z, v.w);
    float hx = __uint_as_float(hp0 << 16);
    float hy = __uint_as_float(hp0 & 0xffff0000u);
    float hz = __uint_as_float(hp1 << 16);
    float hw = __uint_as_float(hp1 & 0xffff0000u);
    uint32_t lp0 = bpack(v.x - hx, v.y - hy);
    uint32_t lp1 = bpack(v.z - hz, v.w - hw);
    *(uint2*)(g_xhi + i4) = make_uint2(hp0, hp1);
    *(uint2*)(g_xlo + i4) = make_uint2(lp0, lp1);
}

// fused + vectorized: y -> (yhi,ylo) + (yThi,yTlo), bf16x2 stores only.
// Block = 16x16 threads, tile = 32(m) x 32(j).
__global__ void k_prep_y(const float* __restrict__ y) {
    __shared__ float tile[32][33];
    int b = blockIdx.z;
    int m0 = blockIdx.y * 32, j0 = blockIdx.x * 32;
    int tx = threadIdx.x, ty = threadIdx.y;   // 16 x 16
    #pragma unroll
    for (int ii = 0; ii < 2; ii++) {
        int i = ty + ii * 16;
        size_t o = ((size_t)b * N_ + m0 + i) * D_ + j0 + 2 * tx;
        float2 v = *(const float2*)(y + o);
        tile[i][2 * tx] = v.x;
        tile[i][2 * tx + 1] = v.y;
        uint32_t hp = bpack(v.x, v.y);
        float h0 = __uint_as_float(hp << 16);
        float h1 = __uint_as_float(hp & 0xffff0000u);
        uint32_t lp = bpack(v.x - h0, v.y - h1);
        *(uint32_t*)(g_yhi + o) = hp;
        *(uint32_t*)(g_ylo + o) = lp;
    }
    __syncthreads();
    #pragma unroll
    for (int jj = 0; jj < 2; jj++) {
        int j = ty + jj * 16;
        float a = tile[2 * tx][j];
        float c = tile[2 * tx + 1][j];
        uint32_t hp = bpack(a, c);
        float h0 = __uint_as_float(hp << 16);
        float h1 = __uint_as_float(hp & 0xffff0000u);
        uint32_t lp = bpack(a - h0, c - h1);
        size_t o = ((size_t)b * D_ + j0 + j) * N_ + m0 + 2 * tx;
        *(uint32_t*)(g_yThi + o) = hp;
        *(uint32_t*)(g_yTlo + o) = lp;
    }
}

// vectorized pos softmax: thread t owns 4 consecutive m (96B contiguous, 6xfloat4)
__global__ void k_pos(const float* __restrict__ coords,
                      const float* __restrict__ pos_emb,
                      const float* __restrict__ p_temp) {
    __shared__ float pe[6];
    __shared__ float sm[8];
    int n = blockIdx.x;
    int t = threadIdx.x;   // 256
    if (t < 6) pe[t] = pos_emb[n * 6 + t];
    __syncthreads();
    float pt = -fabsf(p_temp[0]);

    const float4* src = (const float4*)(coords + (size_t)n * N_ * 6) + t * 6;
    float4 v0 = src[0], v1 = src[1], v2 = src[2];
    float4 v3 = src[3], v4 = src[4], v5 = src[5];

    float lg[4];
    lg[0] = pt * (v0.x * pe[0] + v0.y * pe[1] + v0.z * pe[2] + v0.w * pe[3] + v1.x * pe[4] + v1.y * pe[5]);
    lg[1] = pt * (v1.z * pe[0] + v1.w * pe[1] + v2.x * pe[2] + v2.y * pe[3] + v2.z * pe[4] + v2.w * pe[5]);
    lg[2] = pt * (v3.x * pe[0] + v3.y * pe[1] + v3.z * pe[2] + v3.w * pe[3] + v4.x * pe[4] + v4.y * pe[5]);
    lg[3] = pt * (v4.z * pe[0] + v4.w * pe[1] + v5.x * pe[2] + v5.y * pe[3] + v5.z * pe[4] + v5.w * pe[5]);

    float lmax = fmaxf(fmaxf(lg[0], lg[1]), fmaxf(lg[2], lg[3]));
    float mx = blk_max(lmax, sm);
    float lsum = 0.f;
    #pragma unroll
    for (int i = 0; i < 4; i++) { lg[i] = __expf(lg[i] - mx); lsum += lg[i]; }
    float s = blk_sum(lsum, sm);
    float inv = 1.0f / s;
    float4 o = {lg[0] * inv, lg[1] * inv, lg[2] * inv, lg[3] * inv};
    *(float4*)(g_pos + (size_t)n * N_ + 4 * t) = o;
}

// vectorized mix: thread t owns 4 consecutive m via float4 loads (fp32 scores)
__global__ void k_mix(const float* __restrict__ gating,
                      const float* __restrict__ h_temp,
                      float* __restrict__ heat) {
    __shared__ float sm[8];
    int bn = blockIdx.x;
    int b = bn >> 10;
    int n = bn & (N_ - 1);
    int t = threadIdx.x;

    size_t base0 = ((size_t)(b * 2 + 0) * N_ + n) * N_ + 4 * t;
    size_t base1 = ((size_t)(b * 2 + 1) * N_ + n) * N_ + 4 * t;

    float4 v0 = *(const float4*)(g_scores + base0);
    float4 v1 = *(const float4*)(g_scores + base1);
    float4 vp = *(const float4*)(g_pos + (size_t)n * N_ + 4 * t);
    float s0[4] = {v0.x, v0.y, v0.z, v0.w};
    float s1[4] = {v1.x, v1.y, v1.z, v1.w};
    float pp[4] = {vp.x, vp.y, vp.z, vp.w};

    float lm0 = fmaxf(fmaxf(s0[0], s0[1]), fmaxf(s0[2], s0[3]));
    float lm1 = fmaxf(fmaxf(s1[0], s1[1]), fmaxf(s1[2], s1[3]));
    float mx0 = blk_max(lm0, sm);
    float mx1 = blk_max(lm1, sm);

    float ls0 = 0.f, ls1 = 0.f;
    #pragma unroll
    for (int i = 0; i < 4; i++) {
        s0[i] = __expf(s0[i] - mx0); ls0 += s0[i];
        s1[i] = __expf(s1[i] - mx1); ls1 += s1[i];
    }
    float sum0 = blk_sum(ls0, sm);
    float sum1 = blk_sum(ls1, sm);
    float inv0 = 1.0f / sum0, inv1 = 1.0f / sum1;

    float g = 1.0f / (1.0f + __expf(-gating[0]));
    float og = 1.0f - g;

    float p0[4], p1[4];
    float le0 = 0.f, le1 = 0.f;
    #pragma unroll
    for (int i = 0; i < 4; i++) {
        p0[i] = og * s0[i] * inv0 + g * pp[i];
        p1[i] = og * s1[i] * inv1 + g * pp[i];
        le0 -= p0[i] * __logf(p0[i] + 1e-8f);
        le1 -= p1[i] * __logf(p1[i] + 1e-8f);
    }
    float ent0 = blk_sum(le0, sm);
    float ent1 = blk_sum(le1, sm);

    float ht = h_temp[0];
    float hm0 = 2.0f - 2.0f / (1.0f + __expf(-ht * ent0));
    float hm1 = 2.0f - 2.0f / (1.0f + __expf(-ht * ent1));
    int sel = (hm0 >= hm1) ? 0 : 1;

    const float* ps = sel ? p1 : p0;
    uint32_t hp0 = bpack(ps[0], ps[1]);
    uint32_t hp1 = bpack(ps[2], ps[3]);
    float h0 = __uint_as_float(hp0 << 16);
    float h1 = __uint_as_float(hp0 & 0xffff0000u);
    float h2 = __uint_as_float(hp1 << 16);
    float h3 = __uint_as_float(hp1 & 0xffff0000u);
    uint32_t lp0 = bpack(ps[0] - h0, ps[1] - h1);
    uint32_t lp1 = bpack(ps[2] - h2, ps[3] - h3);
    size_t ob = (size_t)bn * N_ + 4 * t;
    *(uint2*)(g_attnhi + ob) = make_uint2(hp0, hp1);
    *(uint2*)(g_attnlo + ob) = make_uint2(lp0, lp1);

    if (t == 0) heat[bn] = sel ? hm1 : hm0;
}

// ---------------- launch ----------------
extern "C" void kernel_launch(void* const* d_in, const int* in_sizes, int n_in,
                              void* d_out, int out_size) {
    const float* x       = (const float*)d_in[0];
    const float* y       = (const float*)d_in[1];
    const float* coords  = (const float*)d_in[2];
    const float* U       = (const float*)d_in[3];
    const float* S1      = (const float*)d_in[4];
    const float* S2      = (const float*)d_in[5];
    const float* gating  = (const float*)d_in[6];
    const float* h_temp  = (const float*)d_in[7];
    const float* p_temp  = (const float*)d_in[8];
    const float* pos_emb = (const float*)d_in[9];

    float* out  = (float*)d_out;
    float* heat = out + (size_t)B_ * N_ * D_;

    cudaFuncSetAttribute(k_g_w,         cudaFuncAttributeMaxDynamicSharedMemorySize, SMB64);
    cudaFuncSetAttribute(k_gemm_xs,     cudaFuncAttributeMaxDynamicSharedMemorySize, SMB128);
    cudaFuncSetAttribute(k_gemm_scores, cudaFuncAttributeMaxDynamicSharedMemorySize, SMB128);
    cudaFuncSetAttribute(k_gemm_out,    cudaFuncAttributeMaxDynamicSharedMemorySize, SMB64);

    // prep / splits
    k_prep_u<<<(2 * D_ * D_) / 256, 256>>>(U, S1, S2);
    k_transpose_u<<<dim3(D_ / 32, D_ / 32), dim3(32, 8)>>>(U);
    k_split_x<<<(B_ * N_ * D_) / 1024, 256>>>(x);
    k_prep_y<<<dim3(D_ / 32, N_ / 32, B_), dim3(16, 16)>>>(y);
    k_pos<<<N_, 256>>>(coords, pos_emb, p_temp);

    // W = U^T diag|S| U (both branches)  [512 x 256]
    k_g_w<<<dim3(D_ / 64, (2 * D_) / 128), 256, SMB64>>>();

    // xs = x @ W
    k_gemm_xs<<<dim3((2 * D_) / 128, (B_ * N_) / 128), 256, SMB128>>>();

    // patch logits (fp32)
    k_gemm_scores<<<dim3(N_ / 128, N_ / 128, B_ * 2), 256, SMB128>>>();

    // softmax/blend/entropy/route
    k_mix<<<B_ * N_, 256>>>(gating, h_temp, heat);

    // out = attn_sel @ y
    k_gemm_out<<<dim3(D_ / 64, N_ / 128, B_), 256, SMB64>>>(out);
}